// round 3
// baseline (speedup 1.0000x reference)
#include <cuda_runtime.h>
#include <cuda_bf16.h>
#include <cstdint>

// ExiLU_14147622273111: the reference predicate (x>=1001 || x<=447113) is
// tautologically true for all fp32 inputs, so out = in (identity copy).
// Pure HBM-streaming problem: 512 MiB read + 512 MiB write over
// 4096 x 32768 fp32. Bandwidth floor @ ~8 TB/s HBM3e: ~134 us.
//
// Strategy: 128-bit vectorized copy, 4 x float4 per thread with batched
// front loads (per-thread MLP=4, ~16 outstanding 128B lines per warp),
// fully coalesced, exact grid (32,768 blocks x 256 threads covers
// 134,217,728 floats exactly). Graph-capturable, allocation-free.

constexpr int THREADS = 256;
constexpr int V4_PER_THREAD = 4;  // 4 x float4 = 64 B per thread

__global__ void __launch_bounds__(THREADS) copy_f4x4_kernel(
    const float4* __restrict__ in, float4* __restrict__ out, long long n4) {
    long long base = (long long)blockIdx.x * (THREADS * V4_PER_THREAD) + threadIdx.x;

    long long i0 = base;
    long long i1 = base + THREADS;
    long long i2 = base + 2 * THREADS;
    long long i3 = base + 3 * THREADS;

    if (i3 < n4) {
        // Fast path: all four vectors in range (every block for this shape).
        // Front-batch the loads so all 4 LDG.E.128 issue before any store waits.
        float4 v0 = in[i0];
        float4 v1 = in[i1];
        float4 v2 = in[i2];
        float4 v3 = in[i3];
        out[i0] = v0;
        out[i1] = v1;
        out[i2] = v2;
        out[i3] = v3;
    } else {
        if (i0 < n4) out[i0] = in[i0];
        if (i1 < n4) out[i1] = in[i1];
        if (i2 < n4) out[i2] = in[i2];
    }
}

__global__ void __launch_bounds__(THREADS) copy_tail_kernel(
    const float* __restrict__ in, float* __restrict__ out,
    long long start, long long n) {
    long long i = start + (long long)blockIdx.x * blockDim.x + threadIdx.x;
    if (i < n) out[i] = in[i];
}

extern "C" void kernel_launch(void* const* d_in, const int* in_sizes, int n_in,
                              void* d_out, int out_size) {
    const float* in = (const float*)d_in[0];
    float* out = (float*)d_out;
    long long n = (long long)in_sizes[0];   // 4096*32768 = 134,217,728

    long long n4 = n / 4;                                             // 33,554,432
    const long long per_block = (long long)THREADS * V4_PER_THREAD;  // 1024 float4
    long long blocks = (n4 + per_block - 1) / per_block;              // 32,768

    copy_f4x4_kernel<<<(unsigned int)blocks, THREADS>>>(
        (const float4*)in, (float4*)out, n4);

    // Tail in elements (never taken for this shape: n % 4 == 0).
    long long tail_start = n4 * 4;
    long long tail = n - tail_start;
    if (tail > 0) {
        long long tblocks = (tail + THREADS - 1) / THREADS;
        copy_tail_kernel<<<(unsigned int)tblocks, THREADS>>>(in, out, tail_start, n);
    }
}